// round 14
// baseline (speedup 1.0000x reference)
#include <cuda_runtime.h>
#include <cuda_bf16.h>

// N=131072 rows, output (N,4) f32. JAX bisection bbox relabel, BETA=1.
// R14: R13 + (1) warp-aggregated enqueue (ballot + shfl-scan, 2 atomics/warp),
// (2) survivor intervals cached from phase 2a (2b skips the sqrt/div re-init),
// (3) deduped identical logf in the both-neither pick1 path,
// (4) unrolled 2b loop. All computed values bitwise-identical to R13.

#define NROWS 131072
#define TOTAL (2 * NROWS)
#define BLOCK 128
#define MT BLOCK
#define MAXS (MT * 5)
#define BISECT_ITERS 28
#define E_F 2.718281828459045f
#define INV_E_F 0.36787944117144233f
#define SMALL_TH 5.656854249492380f   // 4*sqrt(2)

// flag bits
#define F_ISC    1
#define F_RLL    2
#define F_HASB   4
#define F_SMALL  8
#define F_SB1    16
#define F_SB2    32
#define F_SA1    64
#define F_SA2    128

__device__ __forceinline__ float smooth_l1(float x) {
    float d = fabsf(x);
    return d < 1.0f ? 0.5f * d * d : d - 0.5f;
}
__device__ __forceinline__ float eps_val(float w, float wh, float lwp) {
    return smooth_l1((w - wh) * 0.5f) + smooth_l1(logf(fmaxf(w, 1e-12f)) - lwp);
}

// Branchless sign-carrying eval of eps_prime * max(w,1e-12):
// band-saturated outside [wpc/e, e*wpc]; inside sign(mh*e^t - wpc).
// sigma (w*eps'): flip sign when m < 0.
__device__ __forceinline__ float bis_g(float m, float wh, float wpc,
                                       float hi, float lo, bool sigma) {
    float mh = fmaxf(m, 1e-12f);
    float cA = fminf(fmaxf((m - wh) * 0.5f, -1.0f), 1.0f);
    float t  = 0.5f * cA * mh;
    float gmid = fmaf(mh, __expf(t), -wpc);
    float g = (mh >= hi) ? (t + 1.0f) : ((mh <= lo) ? (t - 1.0f) : gmid);
    if (sigma && m < 0.0f) g = -g;
    return g;
}

// slot k: 0..3 = branchB {c2, c3, c4|c5, c6}, 4 = branchA (cA).
__device__ __forceinline__ void init_slot(int k, float wp, float whB, float whA,
                                          float w0, float& u, float& v,
                                          float& wh, float& wpc, bool& sig) {
    wpc = fmaxf(wp, 1e-12f);
    if (k == 4) {
        u = fmaxf(w0, whA); v = wp; wh = whA; sig = false;
        return;
    }
    wh = whB;
    float base = fmaxf(w0, fmaxf(whB - 2.0f, E_F * wp));
    float ebwp = E_F * wp;
    bool smallB = (whB <= SMALL_TH);
    if (k == 0)      { u = fmaxf(w0, wp);     v = fminf(ebwp, whB); sig = false; }
    else if (k == 1) { u = fmaxf(base, 2.0f); v = whB;              sig = false; }
    else {
        float disc = sqrtf(fmaxf(1.0f - 32.0f / fmaxf(whB * whB, 1e-12f), 0.0f));
        if (k == 2) {
            if (smallB) { u = base; v = fminf(E_F, whB); }
            else        { u = base; v = fminf(fminf(ebwp, whB), whB * 0.25f * (1.0f + disc)); }
        } else {
            u = fmaxf(base, whB * 0.25f * (1.0f - disc));
            v = fminf(ebwp, whB);
        }
        sig = true;
    }
}

__global__ void __launch_bounds__(BLOCK) k_fused(
        const float* __restrict__ pred,
        const float* __restrict__ target,
        const float* __restrict__ crop,
        const float* __restrict__ prop,
        const int*   __restrict__ cases,
        float*       __restrict__ out) {
    __shared__ int   s_cnt, s_nslots, s_cnt2;
    __shared__ int   s_flags[MT];
    __shared__ int   s_task[MT];
    __shared__ float s_wp[MT], s_whB[MT], s_whA[MT], s_w0[MT];
    __shared__ float s_p1[MT], s_p2[MT];
    __shared__ float s_wh1[MT], s_wh2[MT];
    __shared__ short s_desc[MAXS];               // (local<<3)|k
    __shared__ short s_itD[MAXS];                // survivor descriptors
    __shared__ float s_itU[MAXS], s_itV[MAXS];   // survivor intervals
    __shared__ float s_res[MT * 5];

    int tid = threadIdx.x;
    int lane = tid & 31;
    if (tid == 0) { s_cnt = 0; s_nslots = 0; s_cnt2 = 0; }
    __syncthreads();

    // ---------------- phase 1: branchless classify ------------------------
    int t = blockIdx.x * BLOCK + tid;
    int i = t >> 1, a = t & 1;
    const float4 pr = ((const float4*)pred)[i];
    const float4 tg = ((const float4*)target)[i];
    const float4 pp = ((const float4*)prop)[i];
    const float4 cr = ((const float4*)crop)[i];
    const int4   cs = ((const int4*)cases)[i];

    float pd    = a ? pr.y : pr.x;
    float plog  = a ? pr.w : pr.z;
    float td    = a ? tg.y : tg.x;
    float tlog  = a ? tg.w : tg.z;
    float p_d   = a ? pp.y : pp.x;
    float p_o   = a ? pp.w : pp.z;
    float cropa = a ? cr.y : cr.x;
    int   lt    = a ? cs.z : cs.x;
    int   rb    = a ? cs.w : cs.y;
    int type = (lt ? 2 : 0) | (rb ? 1 : 0);

    float to = expf(tlog);
    float po = expf(plog);
    float ca = 0.5f * (p_d + p_o);
    float da = p_o - p_d;
    float q1 = -ca / da;
    float q2 = (cropa - ca) / da;

    bool isR = (type == 1);
    float a1 = isR ? (td - 0.5f * to) : q1;
    float b1 = isR ? q2 : (td + 0.5f * to);
    float wh = isR ? 2.0f * (pd - a1) : 2.0f * (b1 - pd);
    float w0 = b1 - a1;
    float wh1 = 2.0f * (pd - q1);
    float wh2 = 2.0f * (q2 - pd);
    float w0b = q2 - q1;

    bool write = true;
    float dres = td, wres = to;

    // deferred enqueue state
    bool enq = false;
    int  fl = 0, ns = 0;
    float e_wp = 0.f, e_w0 = 0.f, e_whA = 0.f, e_whB = 0.f;
    float e_p1 = 0.f, e_p2 = 0.f, e_wh1 = 0.f, e_wh2 = 0.f;
    int  kfirst = 0;                      // 4 for A-only, 0 for B-package

    if (type == 1 || type == 2) {
        bool bA = fmaxf(w0, wh) < po;
        bool bB = fmaxf(w0, po) < wh;
        if (!bA && !bB) {
            dres = isR ? (a1 + 0.5f * w0) : (b1 - 0.5f * w0);
            wres = w0;
        } else {
            write = false; enq = true;
            fl = (type == 2 ? F_RLL : 0);
            e_wp = po; e_w0 = w0; e_p1 = a1; e_p2 = b1;
            if (bA) { e_whA = wh; ns = 1; kfirst = 4; }
            else {
                fl |= F_HASB;
                bool sm = (wh <= SMALL_TH);
                if (sm) fl |= F_SMALL;
                e_whB = wh; ns = sm ? 3 : 4; kfirst = 0;
            }
        }
    } else if (type == 3) {
        if (pd >= fmaxf(wh1, wh2)) {
            dres = pd; wres = pd;
        } else {
            bool A1 = fmaxf(w0b, wh1) < pd, B1 = fmaxf(w0b, pd) < wh1;
            bool A2 = fmaxf(w0b, wh2) < pd, B2 = fmaxf(w0b, pd) < wh2;
            if (!(A1 | B1 | A2 | B2)) {
                // eps log terms are the identical expression -> evaluate once
                float lwp = logf(fmaxf(pd, 1e-12f));
                float dlog = smooth_l1(logf(fmaxf(w0b, 1e-12f)) - lwp);
                float e1 = smooth_l1((w0b - wh1) * 0.5f) + dlog;
                float e2 = smooth_l1((w0b - wh2) * 0.5f) + dlog;
                bool pick1 = e1 <= e2;
                dres = pick1 ? (q1 + 0.5f * w0b) : (q2 + 0.5f * w0b);
                wres = w0b;
            } else {
                write = false; enq = true;
                fl = F_ISC;
                int sb = B1 ? 1 : (B2 ? 2 : 0);
                int sa = A1 ? 1 : (A2 ? 2 : 0);
                if (sb == 1) fl |= F_SB1; else if (sb == 2) fl |= F_SB2;
                if (sa == 1) fl |= F_SA1; else if (sa == 2) fl |= F_SA2;
                float whB = (sb == 1) ? wh1 : wh2;
                float whA = (sa == 1) ? wh1 : wh2;
                e_wp = pd; e_w0 = w0b; e_p1 = q1; e_p2 = q2;
                e_wh1 = wh1; e_wh2 = wh2; e_whA = whA; e_whB = whB;
                int nb = 0;
                bool sm = (whB <= SMALL_TH);
                if (sb) { fl |= F_HASB; if (sm) fl |= F_SMALL; nb = sm ? 3 : 4; }
                ns = nb + (sa ? 1 : 0);
                kfirst = sb ? 0 : 4;
            }
        }
    }
    if (write) {
        out[i * 4 + a]     = dres;
        out[i * 4 + 2 + a] = wres;
    }

    // warp-aggregated enqueue (2 atomics per warp)
    {
        unsigned m = __ballot_sync(0xffffffffu, enq);
        if (m) {
            int leader = __ffs(m) - 1;
            int nprev = __popc(m & ((1u << lane) - 1u));
            // inclusive shfl scan of ns
            int scan = ns;
#pragma unroll
            for (int dlt = 1; dlt < 32; dlt <<= 1) {
                int x = __shfl_up_sync(0xffffffffu, scan, dlt);
                if (lane >= dlt) scan += x;
            }
            int totslots = __shfl_sync(0xffffffffu, scan, 31);
            int excl = scan - ns;
            int Lbase = 0, Sbase = 0;
            if (lane == leader) {
                Lbase = atomicAdd(&s_cnt, __popc(m));
                Sbase = atomicAdd(&s_nslots, totslots);
            }
            Lbase = __shfl_sync(0xffffffffu, Lbase, leader);
            Sbase = __shfl_sync(0xffffffffu, Sbase, leader);
            if (enq) {
                int L = Lbase + nprev;
                int base = Sbase + excl;
                s_task[L] = t; s_flags[L] = fl;
                s_wp[L] = e_wp; s_w0[L] = e_w0;
                s_p1[L] = e_p1; s_p2[L] = e_p2;
                s_whA[L] = e_whA; s_whB[L] = e_whB;
                s_wh1[L] = e_wh1; s_wh2[L] = e_wh2;
                if (kfirst == 4) {
                    s_desc[base] = (short)((L << 3) | 4);
                } else {
                    int nb = (fl & F_SMALL) ? 3 : 4;
                    for (int k = 0; k < nb; k++)
                        s_desc[base + k] = (short)((L << 3) | k);
                    if (ns > nb) s_desc[base + nb] = (short)((L << 3) | 4);
                }
            }
        }
    }
    __syncthreads();

    // ------ phase 2a: endpoint short-circuit; compact survivors -----------
    int nslots = s_nslots;
    for (int sidx = tid; sidx < nslots; sidx += BLOCK) {
        int d = s_desc[sidx];
        int L = d >> 3, k = d & 7;
        float u, v, whS, wpc; bool sig;
        init_slot(k, s_wp[L], s_whB[L], s_whA[L], s_w0[L], u, v, whS, wpc, sig);
        float hi = E_F * wpc, lo = INV_E_F * wpc;
        float fu = bis_g(u, whS, wpc, hi, lo, sig);
        float fv = bis_g(v, whS, wpc, hi, lo, sig);
        if (fu >= 0.0f) {
            s_res[L * 5 + k] = u;               // reference: f(u0)>=0 -> u0
        } else if (fv <= 0.0f) {
            s_res[L * 5 + k] = v;               // reference: f(v0)<=0 -> v0
        } else {
            int j = atomicAdd(&s_cnt2, 1);
            s_itD[j] = (short)d;
            s_itU[j] = u;
            s_itV[j] = v;
        }
    }
    __syncthreads();

    // ------ phase 2b: dense bisection loops for survivors -----------------
    int cnt2 = s_cnt2;
    for (int j = tid; j < cnt2; j += BLOCK) {
        int d = s_itD[j];
        int L = d >> 3, k = d & 7;
        float u = s_itU[j], v = s_itV[j];
        float wpc = fmaxf(s_wp[L], 1e-12f);
        float whS = (k == 4) ? s_whA[L] : s_whB[L];
        bool sig = (k == 2) | (k == 3);
        float hi = E_F * wpc, lo = INV_E_F * wpc;
#pragma unroll 4
        for (int it = 0; it < BISECT_ITERS; it++) {
            float m = (u + v) * 0.5f;
            bool c = bis_g(m, whS, wpc, hi, lo, sig) >= 0.0f;
            v = c ? m : v;
            u = c ? u : m;
        }
        s_res[L * 5 + k] = (u + v) * 0.5f;      // fu<0<fv -> midpoint
    }
    __syncthreads();

    // ---------------- phase 3: finalize -----------------------------------
    int cnt = s_cnt;
    for (int L = tid; L < cnt; L += BLOCK) {
        int flg = s_flags[L];
        int tg2 = s_task[L];
        int ri = tg2 >> 1, ax = tg2 & 1;
        float wp = s_wp[L], w0s = s_w0[L];
        float lwp = logf(fmaxf(wp, 1e-12f));

        float bw = w0s;
        if (flg & F_HASB) {
            float whB = s_whB[L];
            bool sm = (flg & F_SMALL);
            float bv = eps_val(w0s, whB, lwp);
            float e1 = eps_val(whB, whB, lwp);
            if (e1 < bv) { bv = e1; bw = whB; }
            float e2 = eps_val(s_res[L * 5 + 0], whB, lwp);
            if (e2 < bv) { bv = e2; bw = s_res[L * 5 + 0]; }
            float e3 = eps_val(s_res[L * 5 + 1], whB, lwp);
            if (e3 < bv) { bv = e3; bw = s_res[L * 5 + 1]; }
            float e4 = eps_val(s_res[L * 5 + 2], whB, lwp);
            if (e4 < bv) { bv = e4; bw = s_res[L * 5 + 2]; }
            if (!sm) {
                float e5 = eps_val(s_res[L * 5 + 3], whB, lwp);
                if (e5 < bv) { bv = e5; bw = s_res[L * 5 + 3]; }
            }
        }

        float dr, wr;
        if (!(flg & F_ISC)) {
            wr = (flg & F_HASB) ? bw : s_res[L * 5 + 4];
            float aa1 = s_p1[L], bb1 = s_p2[L];
            dr = (flg & F_RLL) ? (bb1 - 0.5f * wr) : (aa1 + 0.5f * wr);
        } else {
            float a2 = s_p1[L], b2 = s_p2[L];
            float w1h = s_wh1[L], w2h = s_wh2[L];
            int sb = (flg & F_SB1) ? 1 : ((flg & F_SB2) ? 2 : 0);
            int sa = (flg & F_SA1) ? 1 : ((flg & F_SA2) ? 2 : 0);
            float wB = (flg & F_HASB) ? bw : w0s;
            float wA = sa ? s_res[L * 5 + 4] : w0s;
            float w1 = (sb == 1) ? wB : ((sa == 1) ? wA : w0s);
            float w2 = (sb == 2) ? wB : ((sa == 2) ? wA : w0s);
            bool pick1 = eps_val(w1, w1h, lwp) <= eps_val(w2, w2h, lwp);
            dr = pick1 ? (a2 + 0.5f * w1) : (b2 + 0.5f * w2);
            wr = pick1 ? w1 : w2;
        }
        out[ri * 4 + ax]     = dr;
        out[ri * 4 + 2 + ax] = wr;
    }
}

extern "C" void kernel_launch(void* const* d_in, const int* in_sizes, int n_in,
                              void* d_out, int out_size) {
    // metadata order: img, pred, target, crop_shapes, proposal_list, cases, ...
    const float* pred   = (const float*)d_in[1];
    const float* target = (const float*)d_in[2];
    const float* crop   = (const float*)d_in[3];
    const float* prop   = (const float*)d_in[4];
    const int*   cases  = (const int*)d_in[5];
    float* out = (float*)d_out;

    k_fused<<<TOTAL / BLOCK, BLOCK>>>(pred, target, crop, prop, cases, out);
}

// round 15
// speedup vs baseline: 1.0135x; 1.0135x over previous
#include <cuda_runtime.h>
#include <cuda_bf16.h>

// N=131072 rows, output (N,4) f32. JAX bisection bbox relabel, BETA=1.
// R15: R14 + warp-synchronous adaptive early exit in phase 2b: stop once every
// lane's bracket width |v-u| <= 4e-7*max(1,|u|,|v|) (residual == established
// __expf-band noise floor). fabsf handles inverted brackets; loop is
// warp-uniform so the ballot mask is full-warp. Cap stays 28 halvings.

#define NROWS 131072
#define TOTAL (2 * NROWS)
#define BLOCK 128
#define MT BLOCK
#define MAXS (MT * 5)
#define BISECT_ITERS 28
#define E_F 2.718281828459045f
#define INV_E_F 0.36787944117144233f
#define SMALL_TH 5.656854249492380f   // 4*sqrt(2)

// flag bits
#define F_ISC    1
#define F_RLL    2
#define F_HASB   4
#define F_SMALL  8
#define F_SB1    16
#define F_SB2    32
#define F_SA1    64
#define F_SA2    128

__device__ __forceinline__ float smooth_l1(float x) {
    float d = fabsf(x);
    return d < 1.0f ? 0.5f * d * d : d - 0.5f;
}
__device__ __forceinline__ float eps_val(float w, float wh, float lwp) {
    return smooth_l1((w - wh) * 0.5f) + smooth_l1(logf(fmaxf(w, 1e-12f)) - lwp);
}

// Branchless sign-carrying eval of eps_prime * max(w,1e-12):
// band-saturated outside [wpc/e, e*wpc]; inside sign(mh*e^t - wpc).
// sigma (w*eps'): flip sign when m < 0.
__device__ __forceinline__ float bis_g(float m, float wh, float wpc,
                                       float hi, float lo, bool sigma) {
    float mh = fmaxf(m, 1e-12f);
    float cA = fminf(fmaxf((m - wh) * 0.5f, -1.0f), 1.0f);
    float t  = 0.5f * cA * mh;
    float gmid = fmaf(mh, __expf(t), -wpc);
    float g = (mh >= hi) ? (t + 1.0f) : ((mh <= lo) ? (t - 1.0f) : gmid);
    if (sigma && m < 0.0f) g = -g;
    return g;
}

// slot k: 0..3 = branchB {c2, c3, c4|c5, c6}, 4 = branchA (cA).
__device__ __forceinline__ void init_slot(int k, float wp, float whB, float whA,
                                          float w0, float& u, float& v,
                                          float& wh, float& wpc, bool& sig) {
    wpc = fmaxf(wp, 1e-12f);
    if (k == 4) {
        u = fmaxf(w0, whA); v = wp; wh = whA; sig = false;
        return;
    }
    wh = whB;
    float base = fmaxf(w0, fmaxf(whB - 2.0f, E_F * wp));
    float ebwp = E_F * wp;
    bool smallB = (whB <= SMALL_TH);
    if (k == 0)      { u = fmaxf(w0, wp);     v = fminf(ebwp, whB); sig = false; }
    else if (k == 1) { u = fmaxf(base, 2.0f); v = whB;              sig = false; }
    else {
        float disc = sqrtf(fmaxf(1.0f - 32.0f / fmaxf(whB * whB, 1e-12f), 0.0f));
        if (k == 2) {
            if (smallB) { u = base; v = fminf(E_F, whB); }
            else        { u = base; v = fminf(fminf(ebwp, whB), whB * 0.25f * (1.0f + disc)); }
        } else {
            u = fmaxf(base, whB * 0.25f * (1.0f - disc));
            v = fminf(ebwp, whB);
        }
        sig = true;
    }
}

__global__ void __launch_bounds__(BLOCK) k_fused(
        const float* __restrict__ pred,
        const float* __restrict__ target,
        const float* __restrict__ crop,
        const float* __restrict__ prop,
        const int*   __restrict__ cases,
        float*       __restrict__ out) {
    __shared__ int   s_cnt, s_nslots, s_cnt2;
    __shared__ int   s_flags[MT];
    __shared__ int   s_task[MT];
    __shared__ float s_wp[MT], s_whB[MT], s_whA[MT], s_w0[MT];
    __shared__ float s_p1[MT], s_p2[MT];
    __shared__ float s_wh1[MT], s_wh2[MT];
    __shared__ short s_desc[MAXS];               // (local<<3)|k
    __shared__ short s_itD[MAXS];                // survivor descriptors
    __shared__ float s_itU[MAXS], s_itV[MAXS];   // survivor intervals
    __shared__ float s_res[MT * 5];

    int tid = threadIdx.x;
    int lane = tid & 31;
    if (tid == 0) { s_cnt = 0; s_nslots = 0; s_cnt2 = 0; }
    __syncthreads();

    // ---------------- phase 1: branchless classify ------------------------
    int t = blockIdx.x * BLOCK + tid;
    int i = t >> 1, a = t & 1;
    const float4 pr = ((const float4*)pred)[i];
    const float4 tg = ((const float4*)target)[i];
    const float4 pp = ((const float4*)prop)[i];
    const float4 cr = ((const float4*)crop)[i];
    const int4   cs = ((const int4*)cases)[i];

    float pd    = a ? pr.y : pr.x;
    float plog  = a ? pr.w : pr.z;
    float td    = a ? tg.y : tg.x;
    float tlog  = a ? tg.w : tg.z;
    float p_d   = a ? pp.y : pp.x;
    float p_o   = a ? pp.w : pp.z;
    float cropa = a ? cr.y : cr.x;
    int   lt    = a ? cs.z : cs.x;
    int   rb    = a ? cs.w : cs.y;
    int type = (lt ? 2 : 0) | (rb ? 1 : 0);

    float to = expf(tlog);
    float po = expf(plog);
    float ca = 0.5f * (p_d + p_o);
    float da = p_o - p_d;
    float q1 = -ca / da;
    float q2 = (cropa - ca) / da;

    bool isR = (type == 1);
    float a1 = isR ? (td - 0.5f * to) : q1;
    float b1 = isR ? q2 : (td + 0.5f * to);
    float wh = isR ? 2.0f * (pd - a1) : 2.0f * (b1 - pd);
    float w0 = b1 - a1;
    float wh1 = 2.0f * (pd - q1);
    float wh2 = 2.0f * (q2 - pd);
    float w0b = q2 - q1;

    bool write = true;
    float dres = td, wres = to;

    // deferred enqueue state
    bool enq = false;
    int  fl = 0, ns = 0;
    float e_wp = 0.f, e_w0 = 0.f, e_whA = 0.f, e_whB = 0.f;
    float e_p1 = 0.f, e_p2 = 0.f, e_wh1 = 0.f, e_wh2 = 0.f;
    int  kfirst = 0;

    if (type == 1 || type == 2) {
        bool bA = fmaxf(w0, wh) < po;
        bool bB = fmaxf(w0, po) < wh;
        if (!bA && !bB) {
            dres = isR ? (a1 + 0.5f * w0) : (b1 - 0.5f * w0);
            wres = w0;
        } else {
            write = false; enq = true;
            fl = (type == 2 ? F_RLL : 0);
            e_wp = po; e_w0 = w0; e_p1 = a1; e_p2 = b1;
            if (bA) { e_whA = wh; ns = 1; kfirst = 4; }
            else {
                fl |= F_HASB;
                bool sm = (wh <= SMALL_TH);
                if (sm) fl |= F_SMALL;
                e_whB = wh; ns = sm ? 3 : 4; kfirst = 0;
            }
        }
    } else if (type == 3) {
        if (pd >= fmaxf(wh1, wh2)) {
            dres = pd; wres = pd;
        } else {
            bool A1 = fmaxf(w0b, wh1) < pd, B1 = fmaxf(w0b, pd) < wh1;
            bool A2 = fmaxf(w0b, wh2) < pd, B2 = fmaxf(w0b, pd) < wh2;
            if (!(A1 | B1 | A2 | B2)) {
                float lwp = logf(fmaxf(pd, 1e-12f));
                float dlog = smooth_l1(logf(fmaxf(w0b, 1e-12f)) - lwp);
                float e1 = smooth_l1((w0b - wh1) * 0.5f) + dlog;
                float e2 = smooth_l1((w0b - wh2) * 0.5f) + dlog;
                bool pick1 = e1 <= e2;
                dres = pick1 ? (q1 + 0.5f * w0b) : (q2 + 0.5f * w0b);
                wres = w0b;
            } else {
                write = false; enq = true;
                fl = F_ISC;
                int sb = B1 ? 1 : (B2 ? 2 : 0);
                int sa = A1 ? 1 : (A2 ? 2 : 0);
                if (sb == 1) fl |= F_SB1; else if (sb == 2) fl |= F_SB2;
                if (sa == 1) fl |= F_SA1; else if (sa == 2) fl |= F_SA2;
                float whB = (sb == 1) ? wh1 : wh2;
                float whA = (sa == 1) ? wh1 : wh2;
                e_wp = pd; e_w0 = w0b; e_p1 = q1; e_p2 = q2;
                e_wh1 = wh1; e_wh2 = wh2; e_whA = whA; e_whB = whB;
                int nb = 0;
                bool sm = (whB <= SMALL_TH);
                if (sb) { fl |= F_HASB; if (sm) fl |= F_SMALL; nb = sm ? 3 : 4; }
                ns = nb + (sa ? 1 : 0);
                kfirst = sb ? 0 : 4;
            }
        }
    }
    if (write) {
        out[i * 4 + a]     = dres;
        out[i * 4 + 2 + a] = wres;
    }

    // warp-aggregated enqueue (2 atomics per warp)
    {
        unsigned m = __ballot_sync(0xffffffffu, enq);
        if (m) {
            int leader = __ffs(m) - 1;
            int nprev = __popc(m & ((1u << lane) - 1u));
            int scan = ns;
#pragma unroll
            for (int dlt = 1; dlt < 32; dlt <<= 1) {
                int x = __shfl_up_sync(0xffffffffu, scan, dlt);
                if (lane >= dlt) scan += x;
            }
            int totslots = __shfl_sync(0xffffffffu, scan, 31);
            int excl = scan - ns;
            int Lbase = 0, Sbase = 0;
            if (lane == leader) {
                Lbase = atomicAdd(&s_cnt, __popc(m));
                Sbase = atomicAdd(&s_nslots, totslots);
            }
            Lbase = __shfl_sync(0xffffffffu, Lbase, leader);
            Sbase = __shfl_sync(0xffffffffu, Sbase, leader);
            if (enq) {
                int L = Lbase + nprev;
                int base = Sbase + excl;
                s_task[L] = t; s_flags[L] = fl;
                s_wp[L] = e_wp; s_w0[L] = e_w0;
                s_p1[L] = e_p1; s_p2[L] = e_p2;
                s_whA[L] = e_whA; s_whB[L] = e_whB;
                s_wh1[L] = e_wh1; s_wh2[L] = e_wh2;
                if (kfirst == 4) {
                    s_desc[base] = (short)((L << 3) | 4);
                } else {
                    int nb = (fl & F_SMALL) ? 3 : 4;
                    for (int k = 0; k < nb; k++)
                        s_desc[base + k] = (short)((L << 3) | k);
                    if (ns > nb) s_desc[base + nb] = (short)((L << 3) | 4);
                }
            }
        }
    }
    __syncthreads();

    // ------ phase 2a: endpoint short-circuit; compact survivors -----------
    int nslots = s_nslots;
    for (int sidx = tid; sidx < nslots; sidx += BLOCK) {
        int d = s_desc[sidx];
        int L = d >> 3, k = d & 7;
        float u, v, whS, wpc; bool sig;
        init_slot(k, s_wp[L], s_whB[L], s_whA[L], s_w0[L], u, v, whS, wpc, sig);
        float hi = E_F * wpc, lo = INV_E_F * wpc;
        float fu = bis_g(u, whS, wpc, hi, lo, sig);
        float fv = bis_g(v, whS, wpc, hi, lo, sig);
        if (fu >= 0.0f) {
            s_res[L * 5 + k] = u;
        } else if (fv <= 0.0f) {
            s_res[L * 5 + k] = v;
        } else {
            int j = atomicAdd(&s_cnt2, 1);
            s_itD[j] = (short)d;
            s_itU[j] = u;
            s_itV[j] = v;
        }
    }
    __syncthreads();

    // ------ phase 2b: dense bisection with warp-adaptive early exit -------
    int cnt2 = s_cnt2;
    int wbase0 = (tid >> 5) * 32;
    for (int jb = wbase0; jb < cnt2; jb += BLOCK) {
        int j = jb + lane;
        bool act = j < cnt2;
        int d = act ? s_itD[j] : 0;
        int L = d >> 3, k = d & 7;
        float u, v, wpc, whS; bool sig;
        if (act) {
            u = s_itU[j]; v = s_itV[j];
            wpc = fmaxf(s_wp[L], 1e-12f);
            whS = (k == 4) ? s_whA[L] : s_whB[L];
            sig = (k == 2) | (k == 3);
        } else { u = 0.f; v = 0.f; wpc = 1.f; whS = 1.f; sig = false; }
        float hi = E_F * wpc, lo = INV_E_F * wpc;
        float tol = 4e-7f * fmaxf(1.0f, fmaxf(fabsf(u), fabsf(v)));
#pragma unroll 1
        for (int it = 0; it < BISECT_ITERS; it++) {
            bool need = act && (fabsf(v - u) > tol);
            if (!__any_sync(0xffffffffu, need)) break;
            float m = (u + v) * 0.5f;
            bool c = bis_g(m, whS, wpc, hi, lo, sig) >= 0.0f;
            v = c ? m : v;
            u = c ? u : m;
        }
        if (act) s_res[L * 5 + k] = (u + v) * 0.5f;
    }
    __syncthreads();

    // ---------------- phase 3: finalize -----------------------------------
    int cnt = s_cnt;
    for (int L = tid; L < cnt; L += BLOCK) {
        int flg = s_flags[L];
        int tg2 = s_task[L];
        int ri = tg2 >> 1, ax = tg2 & 1;
        float wp = s_wp[L], w0s = s_w0[L];
        float lwp = logf(fmaxf(wp, 1e-12f));

        float bw = w0s;
        if (flg & F_HASB) {
            float whB = s_whB[L];
            bool sm = (flg & F_SMALL);
            float bv = eps_val(w0s, whB, lwp);
            float e1 = eps_val(whB, whB, lwp);
            if (e1 < bv) { bv = e1; bw = whB; }
            float e2 = eps_val(s_res[L * 5 + 0], whB, lwp);
            if (e2 < bv) { bv = e2; bw = s_res[L * 5 + 0]; }
            float e3 = eps_val(s_res[L * 5 + 1], whB, lwp);
            if (e3 < bv) { bv = e3; bw = s_res[L * 5 + 1]; }
            float e4 = eps_val(s_res[L * 5 + 2], whB, lwp);
            if (e4 < bv) { bv = e4; bw = s_res[L * 5 + 2]; }
            if (!sm) {
                float e5 = eps_val(s_res[L * 5 + 3], whB, lwp);
                if (e5 < bv) { bv = e5; bw = s_res[L * 5 + 3]; }
            }
        }

        float dr, wr;
        if (!(flg & F_ISC)) {
            wr = (flg & F_HASB) ? bw : s_res[L * 5 + 4];
            float aa1 = s_p1[L], bb1 = s_p2[L];
            dr = (flg & F_RLL) ? (bb1 - 0.5f * wr) : (aa1 + 0.5f * wr);
        } else {
            float a2 = s_p1[L], b2 = s_p2[L];
            float w1h = s_wh1[L], w2h = s_wh2[L];
            int sb = (flg & F_SB1) ? 1 : ((flg & F_SB2) ? 2 : 0);
            int sa = (flg & F_SA1) ? 1 : ((flg & F_SA2) ? 2 : 0);
            float wB = (flg & F_HASB) ? bw : w0s;
            float wA = sa ? s_res[L * 5 + 4] : w0s;
            float w1 = (sb == 1) ? wB : ((sa == 1) ? wA : w0s);
            float w2 = (sb == 2) ? wB : ((sa == 2) ? wA : w0s);
            bool pick1 = eps_val(w1, w1h, lwp) <= eps_val(w2, w2h, lwp);
            dr = pick1 ? (a2 + 0.5f * w1) : (b2 + 0.5f * w2);
            wr = pick1 ? w1 : w2;
        }
        out[ri * 4 + ax]     = dr;
        out[ri * 4 + 2 + ax] = wr;
    }
}

extern "C" void kernel_launch(void* const* d_in, const int* in_sizes, int n_in,
                              void* d_out, int out_size) {
    // metadata order: img, pred, target, crop_shapes, proposal_list, cases, ...
    const float* pred   = (const float*)d_in[1];
    const float* target = (const float*)d_in[2];
    const float* crop   = (const float*)d_in[3];
    const float* prop   = (const float*)d_in[4];
    const int*   cases  = (const int*)d_in[5];
    float* out = (float*)d_out;

    k_fused<<<TOTAL / BLOCK, BLOCK>>>(pred, target, crop, prop, cases, out);
}

// round 16
// speedup vs baseline: 1.0733x; 1.0590x over previous
#include <cuda_runtime.h>
#include <cuda_bf16.h>

// N=131072 rows, output (N,4) f32. JAX bisection bbox relabel, BETA=1.
// R16: R14 (fixed 28-iter 2b; R15 early-exit reverted — warp-max convergence
// ate the savings) + slot (u,v) bounds precomputed at enqueue (phase 2a loses
// the per-slot base/disc/sqrt/div re-derivation) + 0.5-fold into the clip in
// bis_g (bitwise-identical: pow2 scaling commutes with clamp).

#define NROWS 131072
#define TOTAL (2 * NROWS)
#define BLOCK 128
#define MT BLOCK
#define MAXS (MT * 5)
#define BISECT_ITERS 28
#define E_F 2.718281828459045f
#define INV_E_F 0.36787944117144233f
#define SMALL_TH 5.656854249492380f   // 4*sqrt(2)

// flag bits
#define F_ISC    1
#define F_RLL    2
#define F_HASB   4
#define F_SMALL  8
#define F_SB1    16
#define F_SB2    32
#define F_SA1    64
#define F_SA2    128

__device__ __forceinline__ float smooth_l1(float x) {
    float d = fabsf(x);
    return d < 1.0f ? 0.5f * d * d : d - 0.5f;
}
__device__ __forceinline__ float eps_val(float w, float wh, float lwp) {
    return smooth_l1((w - wh) * 0.5f) + smooth_l1(logf(fmaxf(w, 1e-12f)) - lwp);
}

// Branchless sign-carrying eval of eps_prime * max(w,1e-12).
// t = clip((m-wh)*0.25, +-0.5) * mh  ==  0.5*clip((m-wh)*0.5, +-1) * mh bitwise.
__device__ __forceinline__ float bis_g(float m, float wh, float wpc,
                                       float hi, float lo, bool sigma) {
    float mh = fmaxf(m, 1e-12f);
    float cA = fminf(fmaxf((m - wh) * 0.25f, -0.5f), 0.5f);
    float t  = cA * mh;
    float gmid = fmaf(mh, __expf(t), -wpc);
    float g = (mh >= hi) ? (t + 1.0f) : ((mh <= lo) ? (t - 1.0f) : gmid);
    if (sigma && m < 0.0f) g = -g;
    return g;
}

__global__ void __launch_bounds__(BLOCK) k_fused(
        const float* __restrict__ pred,
        const float* __restrict__ target,
        const float* __restrict__ crop,
        const float* __restrict__ prop,
        const int*   __restrict__ cases,
        float*       __restrict__ out) {
    __shared__ int   s_cnt, s_nslots, s_cnt2;
    __shared__ int   s_flags[MT];
    __shared__ int   s_task[MT];
    __shared__ float s_wp[MT], s_whB[MT], s_whA[MT], s_w0[MT];
    __shared__ float s_p1[MT], s_p2[MT];
    __shared__ float s_wh1[MT], s_wh2[MT];
    __shared__ short s_desc[MAXS];               // (local<<3)|k
    __shared__ float s_slU[MAXS], s_slV[MAXS];   // precomputed slot bounds
    __shared__ short s_itD[MAXS];                // survivor descriptors
    __shared__ float s_itU[MAXS], s_itV[MAXS];   // survivor intervals
    __shared__ float s_res[MT * 5];

    int tid = threadIdx.x;
    int lane = tid & 31;
    if (tid == 0) { s_cnt = 0; s_nslots = 0; s_cnt2 = 0; }
    __syncthreads();

    // ---------------- phase 1: branchless classify ------------------------
    int t = blockIdx.x * BLOCK + tid;
    int i = t >> 1, a = t & 1;
    const float4 pr = ((const float4*)pred)[i];
    const float4 tg = ((const float4*)target)[i];
    const float4 pp = ((const float4*)prop)[i];
    const float4 cr = ((const float4*)crop)[i];
    const int4   cs = ((const int4*)cases)[i];

    float pd    = a ? pr.y : pr.x;
    float plog  = a ? pr.w : pr.z;
    float td    = a ? tg.y : tg.x;
    float tlog  = a ? tg.w : tg.z;
    float p_d   = a ? pp.y : pp.x;
    float p_o   = a ? pp.w : pp.z;
    float cropa = a ? cr.y : cr.x;
    int   lt    = a ? cs.z : cs.x;
    int   rb    = a ? cs.w : cs.y;
    int type = (lt ? 2 : 0) | (rb ? 1 : 0);

    float to = expf(tlog);
    float po = expf(plog);
    float ca = 0.5f * (p_d + p_o);
    float da = p_o - p_d;
    float q1 = -ca / da;
    float q2 = (cropa - ca) / da;

    bool isR = (type == 1);
    float a1 = isR ? (td - 0.5f * to) : q1;
    float b1 = isR ? q2 : (td + 0.5f * to);
    float wh = isR ? 2.0f * (pd - a1) : 2.0f * (b1 - pd);
    float w0 = b1 - a1;
    float wh1 = 2.0f * (pd - q1);
    float wh2 = 2.0f * (q2 - pd);
    float w0b = q2 - q1;

    bool write = true;
    float dres = td, wres = to;

    // deferred enqueue state
    bool enq = false;
    int  fl = 0, ns = 0;
    float e_wp = 0.f, e_w0 = 0.f, e_whA = 0.f, e_whB = 0.f;
    float e_p1 = 0.f, e_p2 = 0.f, e_wh1 = 0.f, e_wh2 = 0.f;
    int  kfirst = 0;

    if (type == 1 || type == 2) {
        bool bA = fmaxf(w0, wh) < po;
        bool bB = fmaxf(w0, po) < wh;
        if (!bA && !bB) {
            dres = isR ? (a1 + 0.5f * w0) : (b1 - 0.5f * w0);
            wres = w0;
        } else {
            write = false; enq = true;
            fl = (type == 2 ? F_RLL : 0);
            e_wp = po; e_w0 = w0; e_p1 = a1; e_p2 = b1;
            if (bA) { e_whA = wh; ns = 1; kfirst = 4; }
            else {
                fl |= F_HASB;
                bool sm = (wh <= SMALL_TH);
                if (sm) fl |= F_SMALL;
                e_whB = wh; ns = sm ? 3 : 4; kfirst = 0;
            }
        }
    } else if (type == 3) {
        if (pd >= fmaxf(wh1, wh2)) {
            dres = pd; wres = pd;
        } else {
            bool A1 = fmaxf(w0b, wh1) < pd, B1 = fmaxf(w0b, pd) < wh1;
            bool A2 = fmaxf(w0b, wh2) < pd, B2 = fmaxf(w0b, pd) < wh2;
            if (!(A1 | B1 | A2 | B2)) {
                float lwp = logf(fmaxf(pd, 1e-12f));
                float dlog = smooth_l1(logf(fmaxf(w0b, 1e-12f)) - lwp);
                float e1 = smooth_l1((w0b - wh1) * 0.5f) + dlog;
                float e2 = smooth_l1((w0b - wh2) * 0.5f) + dlog;
                bool pick1 = e1 <= e2;
                dres = pick1 ? (q1 + 0.5f * w0b) : (q2 + 0.5f * w0b);
                wres = w0b;
            } else {
                write = false; enq = true;
                fl = F_ISC;
                int sb = B1 ? 1 : (B2 ? 2 : 0);
                int sa = A1 ? 1 : (A2 ? 2 : 0);
                if (sb == 1) fl |= F_SB1; else if (sb == 2) fl |= F_SB2;
                if (sa == 1) fl |= F_SA1; else if (sa == 2) fl |= F_SA2;
                float whB = (sb == 1) ? wh1 : wh2;
                float whA = (sa == 1) ? wh1 : wh2;
                e_wp = pd; e_w0 = w0b; e_p1 = q1; e_p2 = q2;
                e_wh1 = wh1; e_wh2 = wh2; e_whA = whA; e_whB = whB;
                int nb = 0;
                bool sm = (whB <= SMALL_TH);
                if (sb) { fl |= F_HASB; if (sm) fl |= F_SMALL; nb = sm ? 3 : 4; }
                ns = nb + (sa ? 1 : 0);
                kfirst = sb ? 0 : 4;
            }
        }
    }
    if (write) {
        out[i * 4 + a]     = dres;
        out[i * 4 + 2 + a] = wres;
    }

    // warp-aggregated enqueue (2 atomics per warp) + slot-bound precompute
    {
        unsigned m = __ballot_sync(0xffffffffu, enq);
        if (m) {
            int leader = __ffs(m) - 1;
            int nprev = __popc(m & ((1u << lane) - 1u));
            int scan = ns;
#pragma unroll
            for (int dlt = 1; dlt < 32; dlt <<= 1) {
                int x = __shfl_up_sync(0xffffffffu, scan, dlt);
                if (lane >= dlt) scan += x;
            }
            int totslots = __shfl_sync(0xffffffffu, scan, 31);
            int excl = scan - ns;
            int Lbase = 0, Sbase = 0;
            if (lane == leader) {
                Lbase = atomicAdd(&s_cnt, __popc(m));
                Sbase = atomicAdd(&s_nslots, totslots);
            }
            Lbase = __shfl_sync(0xffffffffu, Lbase, leader);
            Sbase = __shfl_sync(0xffffffffu, Sbase, leader);
            if (enq) {
                int L = Lbase + nprev;
                int base = Sbase + excl;
                s_task[L] = t; s_flags[L] = fl;
                s_wp[L] = e_wp; s_w0[L] = e_w0;
                s_p1[L] = e_p1; s_p2[L] = e_p2;
                s_whA[L] = e_whA; s_whB[L] = e_whB;
                s_wh1[L] = e_wh1; s_wh2[L] = e_wh2;
                // precompute all slot bounds once (shared base/disc/ebwp)
                int nb = 0;
                if (kfirst != 4) {
                    float whB = e_whB, wp = e_wp, w0e = e_w0;
                    float basev = fmaxf(w0e, fmaxf(whB - 2.0f, E_F * wp));
                    float ebwp = E_F * wp;
                    bool sm = (fl & F_SMALL);
                    float disc = sqrtf(fmaxf(1.0f - 32.0f / fmaxf(whB * whB, 1e-12f), 0.0f));
                    // k=0 (c2)
                    s_desc[base + 0] = (short)((L << 3) | 0);
                    s_slU[base + 0] = fmaxf(w0e, wp);
                    s_slV[base + 0] = fminf(ebwp, whB);
                    // k=1 (c3)
                    s_desc[base + 1] = (short)((L << 3) | 1);
                    s_slU[base + 1] = fmaxf(basev, 2.0f);
                    s_slV[base + 1] = whB;
                    // k=2 (c4 | c5)
                    s_desc[base + 2] = (short)((L << 3) | 2);
                    if (sm) {
                        s_slU[base + 2] = basev;
                        s_slV[base + 2] = fminf(E_F, whB);
                        nb = 3;
                    } else {
                        s_slU[base + 2] = basev;
                        s_slV[base + 2] = fminf(fminf(ebwp, whB),
                                                whB * 0.25f * (1.0f + disc));
                        // k=3 (c6)
                        s_desc[base + 3] = (short)((L << 3) | 3);
                        s_slU[base + 3] = fmaxf(basev, whB * 0.25f * (1.0f - disc));
                        s_slV[base + 3] = fminf(ebwp, whB);
                        nb = 4;
                    }
                }
                if (ns > nb) {                        // A slot
                    s_desc[base + nb] = (short)((L << 3) | 4);
                    s_slU[base + nb] = fmaxf(e_w0, e_whA);
                    s_slV[base + nb] = e_wp;
                }
            }
        }
    }
    __syncthreads();

    // ------ phase 2a: endpoint short-circuit; compact survivors -----------
    int nslots = s_nslots;
    for (int sidx = tid; sidx < nslots; sidx += BLOCK) {
        int d = s_desc[sidx];
        int L = d >> 3, k = d & 7;
        float u = s_slU[sidx], v = s_slV[sidx];
        float wpc = fmaxf(s_wp[L], 1e-12f);
        float whS = (k == 4) ? s_whA[L] : s_whB[L];
        bool sig = (k == 2) | (k == 3);
        float hi = E_F * wpc, lo = INV_E_F * wpc;
        float fu = bis_g(u, whS, wpc, hi, lo, sig);
        float fv = bis_g(v, whS, wpc, hi, lo, sig);
        if (fu >= 0.0f) {
            s_res[L * 5 + k] = u;               // reference: f(u0)>=0 -> u0
        } else if (fv <= 0.0f) {
            s_res[L * 5 + k] = v;               // reference: f(v0)<=0 -> v0
        } else {
            int j = atomicAdd(&s_cnt2, 1);
            s_itD[j] = (short)d;
            s_itU[j] = u;
            s_itV[j] = v;
        }
    }
    __syncthreads();

    // ------ phase 2b: dense bisection loops for survivors -----------------
    int cnt2 = s_cnt2;
    for (int j = tid; j < cnt2; j += BLOCK) {
        int d = s_itD[j];
        int L = d >> 3, k = d & 7;
        float u = s_itU[j], v = s_itV[j];
        float wpc = fmaxf(s_wp[L], 1e-12f);
        float whS = (k == 4) ? s_whA[L] : s_whB[L];
        bool sig = (k == 2) | (k == 3);
        float hi = E_F * wpc, lo = INV_E_F * wpc;
#pragma unroll 4
        for (int it = 0; it < BISECT_ITERS; it++) {
            float m = (u + v) * 0.5f;
            bool c = bis_g(m, whS, wpc, hi, lo, sig) >= 0.0f;
            v = c ? m : v;
            u = c ? u : m;
        }
        s_res[L * 5 + k] = (u + v) * 0.5f;      // fu<0<fv -> midpoint
    }
    __syncthreads();

    // ---------------- phase 3: finalize -----------------------------------
    int cnt = s_cnt;
    for (int L = tid; L < cnt; L += BLOCK) {
        int flg = s_flags[L];
        int tg2 = s_task[L];
        int ri = tg2 >> 1, ax = tg2 & 1;
        float wp = s_wp[L], w0s = s_w0[L];
        float lwp = logf(fmaxf(wp, 1e-12f));

        float bw = w0s;
        if (flg & F_HASB) {
            float whB = s_whB[L];
            bool sm = (flg & F_SMALL);
            float bv = eps_val(w0s, whB, lwp);
            float e1 = eps_val(whB, whB, lwp);
            if (e1 < bv) { bv = e1; bw = whB; }
            float e2 = eps_val(s_res[L * 5 + 0], whB, lwp);
            if (e2 < bv) { bv = e2; bw = s_res[L * 5 + 0]; }
            float e3 = eps_val(s_res[L * 5 + 1], whB, lwp);
            if (e3 < bv) { bv = e3; bw = s_res[L * 5 + 1]; }
            float e4 = eps_val(s_res[L * 5 + 2], whB, lwp);
            if (e4 < bv) { bv = e4; bw = s_res[L * 5 + 2]; }
            if (!sm) {
                float e5 = eps_val(s_res[L * 5 + 3], whB, lwp);
                if (e5 < bv) { bv = e5; bw = s_res[L * 5 + 3]; }
            }
        }

        float dr, wr;
        if (!(flg & F_ISC)) {
            wr = (flg & F_HASB) ? bw : s_res[L * 5 + 4];
            float aa1 = s_p1[L], bb1 = s_p2[L];
            dr = (flg & F_RLL) ? (bb1 - 0.5f * wr) : (aa1 + 0.5f * wr);
        } else {
            float a2 = s_p1[L], b2 = s_p2[L];
            float w1h = s_wh1[L], w2h = s_wh2[L];
            int sb = (flg & F_SB1) ? 1 : ((flg & F_SB2) ? 2 : 0);
            int sa = (flg & F_SA1) ? 1 : ((flg & F_SA2) ? 2 : 0);
            float wB = (flg & F_HASB) ? bw : w0s;
            float wA = sa ? s_res[L * 5 + 4] : w0s;
            float w1 = (sb == 1) ? wB : ((sa == 1) ? wA : w0s);
            float w2 = (sb == 2) ? wB : ((sa == 2) ? wA : w0s);
            bool pick1 = eps_val(w1, w1h, lwp) <= eps_val(w2, w2h, lwp);
            dr = pick1 ? (a2 + 0.5f * w1) : (b2 + 0.5f * w2);
            wr = pick1 ? w1 : w2;
        }
        out[ri * 4 + ax]     = dr;
        out[ri * 4 + 2 + ax] = wr;
    }
}

extern "C" void kernel_launch(void* const* d_in, const int* in_sizes, int n_in,
                              void* d_out, int out_size) {
    // metadata order: img, pred, target, crop_shapes, proposal_list, cases, ...
    const float* pred   = (const float*)d_in[1];
    const float* target = (const float*)d_in[2];
    const float* crop   = (const float*)d_in[3];
    const float* prop   = (const float*)d_in[4];
    const int*   cases  = (const int*)d_in[5];
    float* out = (float*)d_out;

    k_fused<<<TOTAL / BLOCK, BLOCK>>>(pred, target, crop, prop, cases, out);
}

// round 17
// speedup vs baseline: 1.1342x; 1.0567x over previous
#include <cuda_runtime.h>
#include <cuda_bf16.h>

// N=131072 rows, output (N,4) f32. JAX bisection bbox relabel, BETA=1.
// R17: phase 2a folded into the enqueue path — the enqueuing thread already
// has all slot bounds in registers, so it evaluates the endpoint short-circuit
// itself and pushes only survivors. One fewer barrier, -7.6KB smem
// (s_desc/s_slU/s_slV gone). bis_g clip input is now a single FMA with
// precomputed nwh4=-0.25*wh (bitwise-equal). Values identical to R16.

#define NROWS 131072
#define TOTAL (2 * NROWS)
#define BLOCK 128
#define MT BLOCK
#define MAXS (MT * 5)
#define BISECT_ITERS 28
#define E_F 2.718281828459045f
#define INV_E_F 0.36787944117144233f
#define SMALL_TH 5.656854249492380f   // 4*sqrt(2)

// flag bits
#define F_ISC    1
#define F_RLL    2
#define F_HASB   4
#define F_SMALL  8
#define F_SB1    16
#define F_SB2    32
#define F_SA1    64
#define F_SA2    128

__device__ __forceinline__ float smooth_l1(float x) {
    float d = fabsf(x);
    return d < 1.0f ? 0.5f * d * d : d - 0.5f;
}
__device__ __forceinline__ float eps_val(float w, float wh, float lwp) {
    return smooth_l1((w - wh) * 0.5f) + smooth_l1(logf(fmaxf(w, 1e-12f)) - lwp);
}

// Branchless sign-carrying eval of eps_prime * max(w,1e-12).
// nwh4 = -0.25*wh precomputed; fmaf(m,0.25,nwh4) == (m-wh)*0.25 bitwise
// (pow2 scaling commutes with rounding). Clip to +-0.5 == 0.5*clip(.,+-1).
__device__ __forceinline__ float bis_g(float m, float nwh4, float wpc,
                                       float hi, float lo, bool sigma) {
    float mh = fmaxf(m, 1e-12f);
    float cA = fminf(fmaxf(fmaf(m, 0.25f, nwh4), -0.5f), 0.5f);
    float t  = cA * mh;
    float gmid = fmaf(mh, __expf(t), -wpc);
    float g = (mh >= hi) ? (t + 1.0f) : ((mh <= lo) ? (t - 1.0f) : gmid);
    if (sigma && m < 0.0f) g = -g;
    return g;
}

__global__ void __launch_bounds__(BLOCK) k_fused(
        const float* __restrict__ pred,
        const float* __restrict__ target,
        const float* __restrict__ crop,
        const float* __restrict__ prop,
        const int*   __restrict__ cases,
        float*       __restrict__ out) {
    __shared__ int   s_cnt, s_cnt2;
    __shared__ int   s_flags[MT];
    __shared__ int   s_task[MT];
    __shared__ float s_wp[MT], s_whB[MT], s_whA[MT], s_w0[MT];
    __shared__ float s_p1[MT], s_p2[MT];
    __shared__ float s_wh1[MT], s_wh2[MT];
    __shared__ short s_itD[MAXS];                // survivor descriptors
    __shared__ float s_itU[MAXS], s_itV[MAXS];   // survivor intervals
    __shared__ float s_res[MT * 5];

    int tid = threadIdx.x;
    int lane = tid & 31;
    if (tid == 0) { s_cnt = 0; s_cnt2 = 0; }
    __syncthreads();

    // ---------- phase 1: classify + slot endpoint short-circuit -----------
    int t = blockIdx.x * BLOCK + tid;
    int i = t >> 1, a = t & 1;
    const float4 pr = ((const float4*)pred)[i];
    const float4 tg = ((const float4*)target)[i];
    const float4 pp = ((const float4*)prop)[i];
    const float4 cr = ((const float4*)crop)[i];
    const int4   cs = ((const int4*)cases)[i];

    float pd    = a ? pr.y : pr.x;
    float plog  = a ? pr.w : pr.z;
    float td    = a ? tg.y : tg.x;
    float tlog  = a ? tg.w : tg.z;
    float p_d   = a ? pp.y : pp.x;
    float p_o   = a ? pp.w : pp.z;
    float cropa = a ? cr.y : cr.x;
    int   lt    = a ? cs.z : cs.x;
    int   rb    = a ? cs.w : cs.y;
    int type = (lt ? 2 : 0) | (rb ? 1 : 0);

    float to = expf(tlog);
    float po = expf(plog);
    float ca = 0.5f * (p_d + p_o);
    float da = p_o - p_d;
    float q1 = -ca / da;
    float q2 = (cropa - ca) / da;

    bool isR = (type == 1);
    float a1 = isR ? (td - 0.5f * to) : q1;
    float b1 = isR ? q2 : (td + 0.5f * to);
    float wh = isR ? 2.0f * (pd - a1) : 2.0f * (b1 - pd);
    float w0 = b1 - a1;
    float wh1 = 2.0f * (pd - q1);
    float wh2 = 2.0f * (q2 - pd);
    float w0b = q2 - q1;

    bool write = true;
    float dres = td, wres = to;

    bool enq = false;
    int  fl = 0;
    float e_wp = 0.f, e_w0 = 0.f, e_whA = 0.f, e_whB = 0.f;
    float e_p1 = 0.f, e_p2 = 0.f, e_wh1 = 0.f, e_wh2 = 0.f;
    bool hasA = false;

    if (type == 1 || type == 2) {
        bool bA = fmaxf(w0, wh) < po;
        bool bB = fmaxf(w0, po) < wh;
        if (!bA && !bB) {
            dres = isR ? (a1 + 0.5f * w0) : (b1 - 0.5f * w0);
            wres = w0;
        } else {
            write = false; enq = true;
            fl = (type == 2 ? F_RLL : 0);
            e_wp = po; e_w0 = w0; e_p1 = a1; e_p2 = b1;
            if (bA) { e_whA = wh; hasA = true; }
            else {
                fl |= F_HASB;
                if (wh <= SMALL_TH) fl |= F_SMALL;
                e_whB = wh;
            }
        }
    } else if (type == 3) {
        if (pd >= fmaxf(wh1, wh2)) {
            dres = pd; wres = pd;
        } else {
            bool A1 = fmaxf(w0b, wh1) < pd, B1 = fmaxf(w0b, pd) < wh1;
            bool A2 = fmaxf(w0b, wh2) < pd, B2 = fmaxf(w0b, pd) < wh2;
            if (!(A1 | B1 | A2 | B2)) {
                float lwp = logf(fmaxf(pd, 1e-12f));
                float dlog = smooth_l1(logf(fmaxf(w0b, 1e-12f)) - lwp);
                float e1 = smooth_l1((w0b - wh1) * 0.5f) + dlog;
                float e2 = smooth_l1((w0b - wh2) * 0.5f) + dlog;
                bool pick1 = e1 <= e2;
                dres = pick1 ? (q1 + 0.5f * w0b) : (q2 + 0.5f * w0b);
                wres = w0b;
            } else {
                write = false; enq = true;
                fl = F_ISC;
                int sb = B1 ? 1 : (B2 ? 2 : 0);
                int sa = A1 ? 1 : (A2 ? 2 : 0);
                if (sb == 1) fl |= F_SB1; else if (sb == 2) fl |= F_SB2;
                if (sa == 1) fl |= F_SA1; else if (sa == 2) fl |= F_SA2;
                float whB = (sb == 1) ? wh1 : wh2;
                float whA = (sa == 1) ? wh1 : wh2;
                e_wp = pd; e_w0 = w0b; e_p1 = q1; e_p2 = q2;
                e_wh1 = wh1; e_wh2 = wh2; e_whA = whA; e_whB = whB;
                if (sb) { fl |= F_HASB; if (whB <= SMALL_TH) fl |= F_SMALL; }
                hasA = (sa != 0);
            }
        }
    }
    if (write) {
        out[i * 4 + a]     = dres;
        out[i * 4 + 2 + a] = wres;
    }

    // warp-aggregated task-id allocation (1 atomic per warp)
    int L = 0;
    {
        unsigned m = __ballot_sync(0xffffffffu, enq);
        if (m) {
            int leader = __ffs(m) - 1;
            int nprev = __popc(m & ((1u << lane) - 1u));
            int Lbase = 0;
            if (lane == leader) Lbase = atomicAdd(&s_cnt, __popc(m));
            Lbase = __shfl_sync(0xffffffffu, Lbase, leader);
            L = Lbase + nprev;
        }
    }

    if (enq) {
        s_task[L] = t; s_flags[L] = fl;
        s_wp[L] = e_wp; s_w0[L] = e_w0;
        s_p1[L] = e_p1; s_p2[L] = e_p2;
        s_whA[L] = e_whA; s_whB[L] = e_whB;
        s_wh1[L] = e_wh1; s_wh2[L] = e_wh2;

        float wpc = fmaxf(e_wp, 1e-12f);
        float hi = E_F * wpc, lo = INV_E_F * wpc;

        // endpoint short-circuit per slot; push survivors only
        #define DO_SLOT(K, U, V, WHS, SIG) do {                              \
            float _u = (U), _v = (V);                                        \
            float _nwh4 = -0.25f * (WHS);                                    \
            float _fu = bis_g(_u, _nwh4, wpc, hi, lo, (SIG));                \
            float _fv = bis_g(_v, _nwh4, wpc, hi, lo, (SIG));                \
            if (_fu >= 0.0f)      s_res[L * 5 + (K)] = _u;                   \
            else if (_fv <= 0.0f) s_res[L * 5 + (K)] = _v;                   \
            else {                                                           \
                int _j = atomicAdd(&s_cnt2, 1);                              \
                s_itD[_j] = (short)((L << 3) | (K));                         \
                s_itU[_j] = _u; s_itV[_j] = _v;                              \
            }                                                                \
        } while (0)

        if (fl & F_HASB) {
            float whB = e_whB, wp = e_wp, w0e = e_w0;
            float basev = fmaxf(w0e, fmaxf(whB - 2.0f, E_F * wp));
            float ebwp = E_F * wp;
            bool sm = (fl & F_SMALL);
            DO_SLOT(0, fmaxf(w0e, wp), fminf(ebwp, whB), whB, false);   // c2
            DO_SLOT(1, fmaxf(basev, 2.0f), whB, whB, false);            // c3
            if (sm) {
                DO_SLOT(2, basev, fminf(E_F, whB), whB, true);          // c4
            } else {
                float disc = sqrtf(fmaxf(1.0f - 32.0f / fmaxf(whB * whB, 1e-12f), 0.0f));
                DO_SLOT(2, basev,
                        fminf(fminf(ebwp, whB), whB * 0.25f * (1.0f + disc)),
                        whB, true);                                     // c5
                DO_SLOT(3, fmaxf(basev, whB * 0.25f * (1.0f - disc)),
                        fminf(ebwp, whB), whB, true);                   // c6
            }
        }
        if (hasA) {
            DO_SLOT(4, fmaxf(e_w0, e_whA), e_wp, e_whA, false);         // cA
        }
        #undef DO_SLOT
    }
    __syncthreads();

    // ------ phase 2: dense bisection loops for survivors ------------------
    int cnt2 = s_cnt2;
    for (int j = tid; j < cnt2; j += BLOCK) {
        int d = s_itD[j];
        int L2 = d >> 3, k = d & 7;
        float u = s_itU[j], v = s_itV[j];
        float wpc = fmaxf(s_wp[L2], 1e-12f);
        float whS = (k == 4) ? s_whA[L2] : s_whB[L2];
        float nwh4 = -0.25f * whS;
        bool sig = (k == 2) | (k == 3);
        float hi = E_F * wpc, lo = INV_E_F * wpc;
#pragma unroll 4
        for (int it = 0; it < BISECT_ITERS; it++) {
            float m = (u + v) * 0.5f;
            bool c = bis_g(m, nwh4, wpc, hi, lo, sig) >= 0.0f;
            v = c ? m : v;
            u = c ? u : m;
        }
        s_res[L2 * 5 + k] = (u + v) * 0.5f;      // fu<0<fv -> midpoint
    }
    __syncthreads();

    // ---------------- phase 3: finalize -----------------------------------
    int cnt = s_cnt;
    for (int L3 = tid; L3 < cnt; L3 += BLOCK) {
        int flg = s_flags[L3];
        int tg2 = s_task[L3];
        int ri = tg2 >> 1, ax = tg2 & 1;
        float wp = s_wp[L3], w0s = s_w0[L3];
        float lwp = logf(fmaxf(wp, 1e-12f));

        float bw = w0s;
        if (flg & F_HASB) {
            float whB = s_whB[L3];
            bool sm = (flg & F_SMALL);
            float bv = eps_val(w0s, whB, lwp);
            float e1 = eps_val(whB, whB, lwp);
            if (e1 < bv) { bv = e1; bw = whB; }
            float e2 = eps_val(s_res[L3 * 5 + 0], whB, lwp);
            if (e2 < bv) { bv = e2; bw = s_res[L3 * 5 + 0]; }
            float e3 = eps_val(s_res[L3 * 5 + 1], whB, lwp);
            if (e3 < bv) { bv = e3; bw = s_res[L3 * 5 + 1]; }
            float e4 = eps_val(s_res[L3 * 5 + 2], whB, lwp);
            if (e4 < bv) { bv = e4; bw = s_res[L3 * 5 + 2]; }
            if (!sm) {
                float e5 = eps_val(s_res[L3 * 5 + 3], whB, lwp);
                if (e5 < bv) { bv = e5; bw = s_res[L3 * 5 + 3]; }
            }
        }

        float dr, wr;
        if (!(flg & F_ISC)) {
            wr = (flg & F_HASB) ? bw : s_res[L3 * 5 + 4];
            float aa1 = s_p1[L3], bb1 = s_p2[L3];
            dr = (flg & F_RLL) ? (bb1 - 0.5f * wr) : (aa1 + 0.5f * wr);
        } else {
            float a2 = s_p1[L3], b2 = s_p2[L3];
            float w1h = s_wh1[L3], w2h = s_wh2[L3];
            int sb = (flg & F_SB1) ? 1 : ((flg & F_SB2) ? 2 : 0);
            int sa = (flg & F_SA1) ? 1 : ((flg & F_SA2) ? 2 : 0);
            float wB = (flg & F_HASB) ? bw : w0s;
            float wA = sa ? s_res[L3 * 5 + 4] : w0s;
            float w1 = (sb == 1) ? wB : ((sa == 1) ? wA : w0s);
            float w2 = (sb == 2) ? wB : ((sa == 2) ? wA : w0s);
            bool pick1 = eps_val(w1, w1h, lwp) <= eps_val(w2, w2h, lwp);
            dr = pick1 ? (a2 + 0.5f * w1) : (b2 + 0.5f * w2);
            wr = pick1 ? w1 : w2;
        }
        out[ri * 4 + ax]     = dr;
        out[ri * 4 + 2 + ax] = wr;
    }
}

extern "C" void kernel_launch(void* const* d_in, const int* in_sizes, int n_in,
                              void* d_out, int out_size) {
    // metadata order: img, pred, target, crop_shapes, proposal_list, cases, ...
    const float* pred   = (const float*)d_in[1];
    const float* target = (const float*)d_in[2];
    const float* crop   = (const float*)d_in[3];
    const float* prop   = (const float*)d_in[4];
    const int*   cases  = (const int*)d_in[5];
    float* out = (float*)d_out;

    k_fused<<<TOTAL / BLOCK, BLOCK>>>(pred, target, crop, prop, cases, out);
}